// round 5
// baseline (speedup 1.0000x reference)
#include <cuda_runtime.h>
#include <cuda_fp16.h>
#include <math.h>

#define BATCH 2
#define SEQ   2048
#define NH    16
#define HD    64
#define HID   1024
#define F3    3072
#define BS    (BATCH*SEQ)
#define NBH   (BATCH*NH)        // 32

// 0.125 * log2(e)
#define C2EXP 0.1803368801111204f

// permuted k position: pairs (k, k+4) adjacent, 8-word aligned groups
#define KPOS(k) ((((k) >> 3) << 3) + (((k) & 3) << 1) + ((((k) & 7)) >> 2))

// ---------------- scratch (device globals) ---------------------------------
__device__ float  g_qkv[(size_t)BS * F3];                    // 50.3 MB
__device__ float  g_z[NBH * SEQ];
__device__ float  g_colsum[NBH * SEQ];
__device__ __half g_E[(size_t)NBH * SEQ * SEQ];              // 256 MB exp(s)

__device__ __forceinline__ unsigned f2t(float f) {
    unsigned u; asm("cvt.rna.tf32.f32 %0, %1;" : "=r"(u) : "f"(f)); return u;
}
__device__ __forceinline__ float ex2f(float x) {
    float r; asm("ex2.approx.f32 %0, %1;" : "=f"(r) : "f"(x)); return r;
}
__device__ __forceinline__ void mma_tf32(float* c, unsigned a0, unsigned a1,
                                         unsigned a2, unsigned a3,
                                         unsigned b0, unsigned b1) {
    asm volatile(
        "mma.sync.aligned.m16n8k8.row.col.f32.tf32.tf32.f32 "
        "{%0,%1,%2,%3}, {%4,%5,%6,%7}, {%8,%9}, {%0,%1,%2,%3};"
        : "+f"(c[0]), "+f"(c[1]), "+f"(c[2]), "+f"(c[3])
        : "r"(a0), "r"(a1), "r"(a2), "r"(a3), "r"(b0), "r"(b1));
}

// ======================= generic NN GEMM, double-buffered ===================
// A smem: pair-permuted [128][24]; B smem: [16][136] as before.
template <bool SCALE>
__global__ __launch_bounds__(256, 2) void gemm_nn(
    const float* __restrict__ A, const float* __restrict__ B, float* __restrict__ C,
    int K, int lda, int ldb, int ldc, float alpha, const float* __restrict__ cs)
{
    __shared__ unsigned As[128 * 24];
    __shared__ unsigned Bs[16 * 136];

    const int tid = threadIdx.x, lane = tid & 31, wid = tid >> 5;
    const int wm = wid & 1, wn = wid >> 1, qr = lane >> 2, qc = lane & 3;
    const int bm0 = blockIdx.y * 128, bn0 = blockIdx.x * 128;
    const int arow = tid >> 1, akg = (tid & 1);          // A: row, 8-k group
    const int nb = (tid & 31) * 4, kb = tid >> 5;        // B loader

    float4 rA[2], rB[2];

    auto loadAB = [&](int t) {
        const float* ap = A + (long)(bm0 + arow) * lda + t + akg * 8;
        float4 v0 = *(const float4*)(ap);
        float4 v1 = *(const float4*)(ap + 4);
        if (SCALE) {
            int mg = bm0 + arow;
            int b = mg >> 11, s = mg & (SEQ - 1);
            int h = (t + akg * 8) >> 6;
            float sc = cs[(((long)b << 4) + h) * SEQ + s];
            v0.x *= sc; v0.y *= sc; v0.z *= sc; v0.w *= sc;
            v1.x *= sc; v1.y *= sc; v1.z *= sc; v1.w *= sc;
        }
        rA[0] = v0; rA[1] = v1;
#pragma unroll
        for (int rr = 0; rr < 2; rr++) {
            int k = kb + rr * 8;
            rB[rr] = *(const float4*)(B + (long)(t + k) * ldb + bn0 + nb);
        }
    };
    loadAB(0);

    float acc[4][4][4];
#pragma unroll
    for (int i = 0; i < 4; i++)
#pragma unroll
        for (int j = 0; j < 4; j++)
#pragma unroll
            for (int f = 0; f < 4; f++) acc[i][j][f] = 0.f;

#pragma unroll 1
    for (int t = 0; t < K; t += 16) {
        {
            int base = arow * 24 + akg * 8;
            *(uint4*)&As[base] =
                make_uint4(f2t(rA[0].x), f2t(rA[1].x), f2t(rA[0].y), f2t(rA[1].y));
            *(uint4*)&As[base + 4] =
                make_uint4(f2t(rA[0].z), f2t(rA[1].z), f2t(rA[0].w), f2t(rA[1].w));
#pragma unroll
            for (int rr = 0; rr < 2; rr++) {
                int k = kb + rr * 8;
                *(uint4*)&Bs[k * 136 + nb] =
                    make_uint4(f2t(rB[rr].x), f2t(rB[rr].y), f2t(rB[rr].z), f2t(rB[rr].w));
            }
        }
        __syncthreads();
        if (t + 16 < K) loadAB(t + 16);

#pragma unroll
        for (int g = 0; g < 2; g++) {
            int ks = g * 8;
            uint2 pa0[4], pa1[4];
            unsigned bf[4][2];
#pragma unroll
            for (int i = 0; i < 4; i++) {
                int mr = wm * 64 + i * 16 + qr;
                pa0[i] = *(const uint2*)&As[mr * 24 + g * 8 + qc * 2];
                pa1[i] = *(const uint2*)&As[(mr + 8) * 24 + g * 8 + qc * 2];
            }
#pragma unroll
            for (int j = 0; j < 4; j++) {
                int nc = wn * 32 + j * 8 + qr;
                bf[j][0] = Bs[(ks + qc) * 136 + nc];
                bf[j][1] = Bs[(ks + 4 + qc) * 136 + nc];
            }
#pragma unroll
            for (int i = 0; i < 4; i++)
#pragma unroll
                for (int j = 0; j < 4; j++)
                    mma_tf32(acc[i][j], pa0[i].x, pa1[i].x, pa0[i].y, pa1[i].y,
                             bf[j][0], bf[j][1]);
        }
        __syncthreads();
    }

#pragma unroll
    for (int i = 0; i < 4; i++) {
        long row = bm0 + wm * 64 + i * 16 + qr;
#pragma unroll
        for (int j = 0; j < 4; j++) {
            int col = bn0 + wn * 32 + j * 8 + 2 * qc;
            *(float2*)(C + row * ldc + col) =
                make_float2(alpha * acc[i][j][0], alpha * acc[i][j][1]);
            *(float2*)(C + (row + 8) * ldc + col) =
                make_float2(alpha * acc[i][j][2], alpha * acc[i][j][3]);
        }
    }
}

// ======================= QK^T + exp store + Z accumulation ==================
// smem: Qs/Ks pair-permuted [128][72]; one sync before mma loop.
__global__ __launch_bounds__(256, 2) void qk_exp_kernel(
    const float* __restrict__ qkv, float* __restrict__ Z, __half* __restrict__ E)
{
    extern __shared__ char dyn[];
    unsigned* Qs = (unsigned*)dyn;                        // 128*72 words = 36 KB
    unsigned* Ks = (unsigned*)(dyn + 36864);              // 36 KB
    float* s_red = (float*)(dyn + 73728);                 // 4*128 floats

    const int tid = threadIdx.x, lane = tid & 31, wid = tid >> 5;
    const int wm = wid & 1, wn = wid >> 1, qr = lane >> 2, qc = lane & 3;
    const int bz = blockIdx.z;
    const int b = bz >> 4, h = bz & 15;
    const float* Qp = qkv + (long)b * SEQ * F3 + h * HD;
    const float* Kp = Qp + HID;
    const int bm0 = blockIdx.y * 128, bn0 = blockIdx.x * 128;

    const int cg = tid & 7, rb = tid >> 3;                // 8 col-groups, 32 rows
#pragma unroll
    for (int r = 0; r < 4; r++) {
        int row = rb + r * 32;
        const float* qrow = Qp + (long)(bm0 + row) * F3 + cg * 8;
        const float* krow = Kp + (long)(bn0 + row) * F3 + cg * 8;
        float4 q0 = *(const float4*)(qrow), q1 = *(const float4*)(qrow + 4);
        float4 k0 = *(const float4*)(krow), k1 = *(const float4*)(krow + 4);
        int base = row * 72 + cg * 8;
        *(uint4*)&Qs[base]     = make_uint4(f2t(q0.x), f2t(q1.x), f2t(q0.y), f2t(q1.y));
        *(uint4*)&Qs[base + 4] = make_uint4(f2t(q0.z), f2t(q1.z), f2t(q0.w), f2t(q1.w));
        *(uint4*)&Ks[base]     = make_uint4(f2t(k0.x), f2t(k1.x), f2t(k0.y), f2t(k1.y));
        *(uint4*)&Ks[base + 4] = make_uint4(f2t(k0.z), f2t(k1.z), f2t(k0.w), f2t(k1.w));
    }
    __syncthreads();

    float acc[4][4][4];
#pragma unroll
    for (int i = 0; i < 4; i++)
#pragma unroll
        for (int j = 0; j < 4; j++)
#pragma unroll
            for (int f = 0; f < 4; f++) acc[i][j][f] = 0.f;

#pragma unroll
    for (int g = 0; g < 8; g++) {
        uint2 pa0[4], pa1[4], pb[4];
#pragma unroll
        for (int i = 0; i < 4; i++) {
            int mr = wm * 64 + i * 16 + qr;
            pa0[i] = *(const uint2*)&Qs[mr * 72 + g * 8 + qc * 2];
            pa1[i] = *(const uint2*)&Qs[(mr + 8) * 72 + g * 8 + qc * 2];
        }
#pragma unroll
        for (int j = 0; j < 4; j++) {
            int nc = wn * 32 + j * 8 + qr;
            pb[j] = *(const uint2*)&Ks[nc * 72 + g * 8 + qc * 2];
        }
#pragma unroll
        for (int i = 0; i < 4; i++)
#pragma unroll
            for (int j = 0; j < 4; j++)
                mma_tf32(acc[i][j], pa0[i].x, pa1[i].x, pa0[i].y, pa1[i].y,
                         pb[j].x, pb[j].y);
    }

    // epilogue: exp -> E (fp16), row-sum partials -> Z (atomics)
    __half* Eh = E + (size_t)bz * SEQ * SEQ;
    float lz[4][2];
#pragma unroll
    for (int i = 0; i < 4; i++)
#pragma unroll
        for (int h2 = 0; h2 < 2; h2++) {
            int row = bm0 + wm * 64 + i * 16 + h2 * 8 + qr;
            __half* erow = Eh + (size_t)row * SEQ + bn0 + wn * 32 + 2 * qc;
            float z = 0.f;
#pragma unroll
            for (int j = 0; j < 4; j++) {
                float e0 = ex2f(acc[i][j][2 * h2]     * C2EXP);
                float e1 = ex2f(acc[i][j][2 * h2 + 1] * C2EXP);
                z += e0 + e1;
                *(__half2*)(erow + j * 8) = __floats2half2_rn(e0, e1);
            }
            lz[i][h2] = z;
        }
#pragma unroll
    for (int d = 1; d <= 2; d <<= 1)
#pragma unroll
        for (int i = 0; i < 4; i++)
#pragma unroll
            for (int h2 = 0; h2 < 2; h2++)
                lz[i][h2] += __shfl_xor_sync(0xffffffffu, lz[i][h2], d);
    if (qc == 0)
#pragma unroll
        for (int i = 0; i < 4; i++)
#pragma unroll
            for (int h2 = 0; h2 < 2; h2++)
                s_red[wn * 128 + wm * 64 + i * 16 + h2 * 8 + qr] = lz[i][h2];
    __syncthreads();
    if (tid < 128) {
        float z = s_red[tid] + s_red[128 + tid] + s_red[256 + tid] + s_red[384 + tid];
        atomicAdd(&Z[(long)bz * SEQ + bm0 + tid], z);
    }
}

// ======================= colsum: streaming reduction over E =================
// grid (SEQ/512, NBH), 256 threads; each thread owns 2 adjacent k columns.
__global__ __launch_bounds__(256, 4) void colsum_kernel(
    const __half* __restrict__ E, const float* __restrict__ Z, float* __restrict__ cs)
{
    const int tid = threadIdx.x;
    const int bz = blockIdx.y;
    const int k0 = blockIdx.x * 512 + tid * 2;
    const __half2* Ep = (const __half2*)(E + (size_t)bz * SEQ * SEQ) + (k0 >> 1);
    __shared__ float s_iz[256];

    float ax = 0.f, ay = 0.f;
    for (int q0 = 0; q0 < SEQ; q0 += 256) {
        __syncthreads();
        s_iz[tid] = 1.0f / Z[(long)bz * SEQ + q0 + tid];
        __syncthreads();
#pragma unroll 8
        for (int q = 0; q < 256; q++) {
            float iz = s_iz[q];
            float2 ef = __half22float2(Ep[(size_t)(q0 + q) * (SEQ / 2)]);
            ax += ef.x * iz;
            ay += ef.y * iz;
        }
    }
    *(float2*)(cs + (long)bz * SEQ + k0) = make_float2(ax, ay);
}

// ---------------- zero Z ----------------------------------------------------
__global__ void zero_kernel(float* __restrict__ z)
{
    int i = blockIdx.x * 256 + threadIdx.x;
    if (i < NBH * SEQ) z[i] = 0.f;
}

// ---------------- launcher --------------------------------------------------
#define QK_SMEM (73728 + 2048)

extern "C" void kernel_launch(void* const* d_in, const int* in_sizes, int n_in,
                              void* d_out, int out_size)
{
    const float* x     = (const float*)d_in[0];
    const float* w_qkv = (const float*)d_in[1];
    const float* w_o   = (const float*)d_in[2];
    float* out = (float*)d_out;

    float *p_qkv, *p_z, *p_cs;
    __half* p_E;
    cudaGetSymbolAddress((void**)&p_qkv, g_qkv);
    cudaGetSymbolAddress((void**)&p_z,   g_z);
    cudaGetSymbolAddress((void**)&p_cs,  g_colsum);
    cudaGetSymbolAddress((void**)&p_E,   g_E);

    cudaFuncSetAttribute(qk_exp_kernel, cudaFuncAttributeMaxDynamicSharedMemorySize, QK_SMEM);

    dim3 blk(256);

    // 0. zero Z accumulators
    zero_kernel<<<(NBH * SEQ + 255) / 256, blk>>>(p_z);

    // 1. qkv = x @ w_qkv
    gemm_nn<false><<<dim3(F3 / 128, BS / 128), blk>>>(
        x, w_qkv, p_qkv, HID, HID, F3, F3, 1.0f, nullptr);

    // 2. scores pass: E = exp(QK^T/8) (fp16), Z row-sums
    qk_exp_kernel<<<dim3(SEQ / 128, SEQ / 128, NBH), blk, QK_SMEM>>>(p_qkv, p_z, p_E);

    // 3. colsum[k] = sum_q E[q][k] / Z[q]   (streaming, no atomics)
    colsum_kernel<<<dim3(SEQ / 512, NBH), blk>>>(p_E, p_z, p_cs);

    // 4. out = (v * colsum) @ w_o  (scale fused into A-load)
    gemm_nn<true><<<dim3(HID / 128, BS / 128), blk>>>(
        p_qkv + 2 * HID, w_o, out, HID, F3, HID, HID, 1.0f, p_cs);
}

// round 6
// speedup vs baseline: 1.1191x; 1.1191x over previous
#include <cuda_runtime.h>
#include <math.h>

#define BATCH 2
#define SEQ   2048
#define NH    16
#define HD    64
#define HID   1024
#define F3    3072
#define BS    (BATCH*SEQ)
#define NBH   (BATCH*NH)        // 32

// 0.125 * log2(e)
#define C2EXP 0.1803368801111204f

// ---------------- scratch (device globals) ---------------------------------
__device__ float g_qkv[(size_t)BS * F3];                 // 50.3 MB
__device__ float g_z[NBH * SEQ];
__device__ float g_colsum[NBH * SEQ];

__device__ __forceinline__ unsigned f2t(float f) {
    unsigned u; asm("cvt.rna.tf32.f32 %0, %1;" : "=r"(u) : "f"(f)); return u;
}
__device__ __forceinline__ float ex2f(float x) {
    float r; asm("ex2.approx.f32 %0, %1;" : "=f"(r) : "f"(x)); return r;
}
__device__ __forceinline__ void mma_tf32(float* c, unsigned a0, unsigned a1,
                                         unsigned a2, unsigned a3,
                                         unsigned b0, unsigned b1) {
    asm volatile(
        "mma.sync.aligned.m16n8k8.row.col.f32.tf32.tf32.f32 "
        "{%0,%1,%2,%3}, {%4,%5,%6,%7}, {%8,%9}, {%0,%1,%2,%3};"
        : "+f"(c[0]), "+f"(c[1]), "+f"(c[2]), "+f"(c[3])
        : "r"(a0), "r"(a1), "r"(a2), "r"(a3), "r"(b0), "r"(b1));
}

// ======================= generic NN GEMM, double-buffered ===================
// A smem: pair-permuted [128][24] (LDS.64 fragment loads); B smem [16][136].
template <bool SCALE>
__global__ __launch_bounds__(256, 2) void gemm_nn(
    const float* __restrict__ A, const float* __restrict__ B, float* __restrict__ C,
    int K, int lda, int ldb, int ldc, float alpha, const float* __restrict__ cs)
{
    __shared__ unsigned As[128 * 24];
    __shared__ unsigned Bs[16 * 136];

    const int tid = threadIdx.x, lane = tid & 31, wid = tid >> 5;
    const int wm = wid & 1, wn = wid >> 1, qr = lane >> 2, qc = lane & 3;
    const int bm0 = blockIdx.y * 128, bn0 = blockIdx.x * 128;
    const int arow = tid >> 1, akg = (tid & 1);
    const int nb = (tid & 31) * 4, kb = tid >> 5;

    float4 rA[2], rB[2];

    auto loadAB = [&](int t) {
        const float* ap = A + (long)(bm0 + arow) * lda + t + akg * 8;
        float4 v0 = *(const float4*)(ap);
        float4 v1 = *(const float4*)(ap + 4);
        if (SCALE) {
            int mg = bm0 + arow;
            int b = mg >> 11, s = mg & (SEQ - 1);
            int h = (t + akg * 8) >> 6;
            float sc = cs[(((long)b << 4) + h) * SEQ + s];
            v0.x *= sc; v0.y *= sc; v0.z *= sc; v0.w *= sc;
            v1.x *= sc; v1.y *= sc; v1.z *= sc; v1.w *= sc;
        }
        rA[0] = v0; rA[1] = v1;
#pragma unroll
        for (int rr = 0; rr < 2; rr++) {
            int k = kb + rr * 8;
            rB[rr] = *(const float4*)(B + (long)(t + k) * ldb + bn0 + nb);
        }
    };
    loadAB(0);

    float acc[4][4][4];
#pragma unroll
    for (int i = 0; i < 4; i++)
#pragma unroll
        for (int j = 0; j < 4; j++)
#pragma unroll
            for (int f = 0; f < 4; f++) acc[i][j][f] = 0.f;

#pragma unroll 1
    for (int t = 0; t < K; t += 16) {
        {
            int base = arow * 24 + akg * 8;
            *(uint4*)&As[base] =
                make_uint4(f2t(rA[0].x), f2t(rA[1].x), f2t(rA[0].y), f2t(rA[1].y));
            *(uint4*)&As[base + 4] =
                make_uint4(f2t(rA[0].z), f2t(rA[1].z), f2t(rA[0].w), f2t(rA[1].w));
#pragma unroll
            for (int rr = 0; rr < 2; rr++) {
                int k = kb + rr * 8;
                *(uint4*)&Bs[k * 136 + nb] =
                    make_uint4(f2t(rB[rr].x), f2t(rB[rr].y), f2t(rB[rr].z), f2t(rB[rr].w));
            }
        }
        __syncthreads();
        if (t + 16 < K) loadAB(t + 16);

#pragma unroll
        for (int g = 0; g < 2; g++) {
            int ks = g * 8;
            uint2 pa0[4], pa1[4];
            unsigned bf[4][2];
#pragma unroll
            for (int i = 0; i < 4; i++) {
                int mr = wm * 64 + i * 16 + qr;
                pa0[i] = *(const uint2*)&As[mr * 24 + g * 8 + qc * 2];
                pa1[i] = *(const uint2*)&As[(mr + 8) * 24 + g * 8 + qc * 2];
            }
#pragma unroll
            for (int j = 0; j < 4; j++) {
                int nc = wn * 32 + j * 8 + qr;
                bf[j][0] = Bs[(ks + qc) * 136 + nc];
                bf[j][1] = Bs[(ks + 4 + qc) * 136 + nc];
            }
#pragma unroll
            for (int i = 0; i < 4; i++)
#pragma unroll
                for (int j = 0; j < 4; j++)
                    mma_tf32(acc[i][j], pa0[i].x, pa1[i].x, pa0[i].y, pa1[i].y,
                             bf[j][0], bf[j][1]);
        }
        __syncthreads();
    }

#pragma unroll
    for (int i = 0; i < 4; i++) {
        long row = bm0 + wm * 64 + i * 16 + qr;
#pragma unroll
        for (int j = 0; j < 4; j++) {
            int col = bn0 + wn * 32 + j * 8 + 2 * qc;
            *(float2*)(C + row * ldc + col) =
                make_float2(alpha * acc[i][j][0], alpha * acc[i][j][1]);
            *(float2*)(C + (row + 8) * ldc + col) =
                make_float2(alpha * acc[i][j][2], alpha * acc[i][j][3]);
        }
    }
}

// ======================= QK^T pass (K=64, one sync, paired LDS) =============
// MODE 1: Z[q] += sum_k exp(s_qk)
// MODE 2: colsum[k] += sum_q exp(s_qk)/Z[q]
template <int MODE>
__global__ __launch_bounds__(256, 2) void qk_kernel(
    const float* __restrict__ qkv, float* __restrict__ Z, float* __restrict__ colsum)
{
    extern __shared__ char dyn[];
    unsigned* Qs = (unsigned*)dyn;                        // 128*72 words = 36 KB
    unsigned* Ks = (unsigned*)(dyn + 36864);              // 36 KB
    float* s_red = (float*)(dyn + 73728);                 // 512 floats (MODE1)
    float* s_iz  = (float*)(dyn + 73728);                 // 128 floats (MODE2)

    const int tid = threadIdx.x, lane = tid & 31, wid = tid >> 5;
    const int wm = wid & 1, wn = wid >> 1, qr = lane >> 2, qc = lane & 3;
    const int bz = blockIdx.z;
    const int b = bz >> 4, h = bz & 15;
    const float* Qp = qkv + (long)b * SEQ * F3 + h * HD;
    const float* Kp = Qp + HID;
    const int bm0 = blockIdx.y * 128, bn0 = blockIdx.x * 128;

    const int cg = tid & 7, rb = tid >> 3;
#pragma unroll
    for (int r = 0; r < 4; r++) {
        int row = rb + r * 32;
        const float* qrow = Qp + (long)(bm0 + row) * F3 + cg * 8;
        const float* krow = Kp + (long)(bn0 + row) * F3 + cg * 8;
        float4 q0 = *(const float4*)(qrow), q1 = *(const float4*)(qrow + 4);
        float4 k0 = *(const float4*)(krow), k1 = *(const float4*)(krow + 4);
        int base = row * 72 + cg * 8;
        *(uint4*)&Qs[base]     = make_uint4(f2t(q0.x), f2t(q1.x), f2t(q0.y), f2t(q1.y));
        *(uint4*)&Qs[base + 4] = make_uint4(f2t(q0.z), f2t(q1.z), f2t(q0.w), f2t(q1.w));
        *(uint4*)&Ks[base]     = make_uint4(f2t(k0.x), f2t(k1.x), f2t(k0.y), f2t(k1.y));
        *(uint4*)&Ks[base + 4] = make_uint4(f2t(k0.z), f2t(k1.z), f2t(k0.w), f2t(k1.w));
    }
    if (MODE == 2 && tid < 128)
        s_iz[tid] = 1.0f / Z[(long)bz * SEQ + bm0 + tid];
    __syncthreads();

    float acc[4][4][4];
#pragma unroll
    for (int i = 0; i < 4; i++)
#pragma unroll
        for (int j = 0; j < 4; j++)
#pragma unroll
            for (int f = 0; f < 4; f++) acc[i][j][f] = 0.f;

    float izreg[4][2];
    if (MODE == 2) {
#pragma unroll
        for (int i = 0; i < 4; i++)
#pragma unroll
            for (int h2 = 0; h2 < 2; h2++)
                izreg[i][h2] = s_iz[wm * 64 + i * 16 + h2 * 8 + qr];
    }

#pragma unroll
    for (int g = 0; g < 8; g++) {
        uint2 pa0[4], pa1[4], pb[4];
#pragma unroll
        for (int i = 0; i < 4; i++) {
            int mr = wm * 64 + i * 16 + qr;
            pa0[i] = *(const uint2*)&Qs[mr * 72 + g * 8 + qc * 2];
            pa1[i] = *(const uint2*)&Qs[(mr + 8) * 72 + g * 8 + qc * 2];
        }
#pragma unroll
        for (int j = 0; j < 4; j++) {
            int nc = wn * 32 + j * 8 + qr;
            pb[j] = *(const uint2*)&Ks[nc * 72 + g * 8 + qc * 2];
        }
#pragma unroll
        for (int i = 0; i < 4; i++)
#pragma unroll
            for (int j = 0; j < 4; j++)
                mma_tf32(acc[i][j], pa0[i].x, pa1[i].x, pa0[i].y, pa1[i].y,
                         pb[j].x, pb[j].y);
    }

    if (MODE == 1) {
        float lz[4][2];
#pragma unroll
        for (int i = 0; i < 4; i++)
#pragma unroll
            for (int h2 = 0; h2 < 2; h2++) {
                float z = 0.f;
#pragma unroll
                for (int j = 0; j < 4; j++) {
                    z += ex2f(acc[i][j][2 * h2]     * C2EXP);
                    z += ex2f(acc[i][j][2 * h2 + 1] * C2EXP);
                }
                lz[i][h2] = z;
            }
#pragma unroll
        for (int d = 1; d <= 2; d <<= 1)
#pragma unroll
            for (int i = 0; i < 4; i++)
#pragma unroll
                for (int h2 = 0; h2 < 2; h2++)
                    lz[i][h2] += __shfl_xor_sync(0xffffffffu, lz[i][h2], d);
        __syncthreads();
        if (qc == 0)
#pragma unroll
            for (int i = 0; i < 4; i++)
#pragma unroll
                for (int h2 = 0; h2 < 2; h2++)
                    s_red[wn * 128 + wm * 64 + i * 16 + h2 * 8 + qr] = lz[i][h2];
        __syncthreads();
        if (tid < 128) {
            float z = s_red[tid] + s_red[128 + tid] + s_red[256 + tid] + s_red[384 + tid];
            atomicAdd(&Z[(long)bz * SEQ + bm0 + tid], z);
        }
    }

    if (MODE == 2) {
        float cs[4][2];
#pragma unroll
        for (int j = 0; j < 4; j++) { cs[j][0] = 0.f; cs[j][1] = 0.f; }
#pragma unroll
        for (int i = 0; i < 4; i++)
#pragma unroll
            for (int h2 = 0; h2 < 2; h2++) {
                float iz = izreg[i][h2];
#pragma unroll
                for (int j = 0; j < 4; j++) {
                    cs[j][0] += ex2f(acc[i][j][2 * h2]     * C2EXP) * iz;
                    cs[j][1] += ex2f(acc[i][j][2 * h2 + 1] * C2EXP) * iz;
                }
            }
#pragma unroll
        for (int d = 4; d <= 16; d <<= 1)
#pragma unroll
            for (int j = 0; j < 4; j++) {
                cs[j][0] += __shfl_xor_sync(0xffffffffu, cs[j][0], d);
                cs[j][1] += __shfl_xor_sync(0xffffffffu, cs[j][1], d);
            }
        if (qr == 0) {
#pragma unroll
            for (int j = 0; j < 4; j++) {
                int col = bn0 + wn * 32 + j * 8 + 2 * qc;
                atomicAdd(&colsum[(long)bz * SEQ + col],     cs[j][0]);
                atomicAdd(&colsum[(long)bz * SEQ + col + 1], cs[j][1]);
            }
        }
    }
}

// ---------------- zero accumulators ----------------------------------------
__global__ void zero_kernel(float* __restrict__ z, float* __restrict__ cs)
{
    int i = blockIdx.x * 256 + threadIdx.x;
    if (i < NBH * SEQ) { z[i] = 0.f; cs[i] = 0.f; }
}

// ---------------- launcher --------------------------------------------------
#define QK_SMEM (73728 + 2048)

extern "C" void kernel_launch(void* const* d_in, const int* in_sizes, int n_in,
                              void* d_out, int out_size)
{
    const float* x     = (const float*)d_in[0];
    const float* w_qkv = (const float*)d_in[1];
    const float* w_o   = (const float*)d_in[2];
    float* out = (float*)d_out;

    float *p_qkv, *p_z, *p_cs;
    cudaGetSymbolAddress((void**)&p_qkv, g_qkv);
    cudaGetSymbolAddress((void**)&p_z,   g_z);
    cudaGetSymbolAddress((void**)&p_cs,  g_colsum);

    cudaFuncSetAttribute(qk_kernel<1>, cudaFuncAttributeMaxDynamicSharedMemorySize, QK_SMEM);
    cudaFuncSetAttribute(qk_kernel<2>, cudaFuncAttributeMaxDynamicSharedMemorySize, QK_SMEM);

    dim3 blk(256);

    // 0. zero Z + colsum accumulators
    zero_kernel<<<(NBH * SEQ + 255) / 256, blk>>>(p_z, p_cs);

    // 1. qkv = x @ w_qkv
    gemm_nn<false><<<dim3(F3 / 128, BS / 128), blk>>>(
        x, w_qkv, p_qkv, HID, HID, F3, F3, 1.0f, nullptr);

    // 2. pass 1: Z[q] = sum_k exp(q.k/8)
    qk_kernel<1><<<dim3(SEQ / 128, SEQ / 128, NBH), blk, QK_SMEM>>>(p_qkv, p_z, nullptr);

    // 3. pass 2: colsum[k] = sum_q exp(q.k/8)/Z[q]
    qk_kernel<2><<<dim3(SEQ / 128, SEQ / 128, NBH), blk, QK_SMEM>>>(p_qkv, p_z, p_cs);

    // 4. out = (v * colsum) @ w_o  (scale fused into A-load)
    gemm_nn<true><<<dim3(HID / 128, BS / 128), blk>>>(
        p_qkv + 2 * HID, w_o, out, HID, F3, HID, HID, 1.0f, p_cs);
}

// round 7
// speedup vs baseline: 1.4121x; 1.2618x over previous
#include <cuda_runtime.h>
#include <cuda_bf16.h>
#include <math.h>

#define BATCH 2
#define SEQ   2048
#define NH    16
#define HD    64
#define HID   1024
#define F3    3072
#define BS    (BATCH*SEQ)
#define NBH   (BATCH*NH)        // 32

// 0.125 * log2(e)
#define C2EXP 0.1803368801111204f

// ---------------- scratch (device globals) ---------------------------------
__device__ float g_qkv[(size_t)BS * F3];                 // 50.3 MB
__device__ float g_z[NBH * SEQ];
__device__ float g_colsum[NBH * SEQ];
// bf16 copies of Q and K, 16B-aligned (uint4 = 8 halves)
__device__ uint4 g_q16[(size_t)BS * HID / 8];            // 8.4 MB
__device__ uint4 g_k16[(size_t)BS * HID / 8];            // 8.4 MB

__device__ __forceinline__ unsigned f2t(float f) {
    unsigned u; asm("cvt.rna.tf32.f32 %0, %1;" : "=r"(u) : "f"(f)); return u;
}
__device__ __forceinline__ float ex2f(float x) {
    float r; asm("ex2.approx.f32 %0, %1;" : "=f"(r) : "f"(x)); return r;
}
__device__ __forceinline__ unsigned sptr(const void* p) {
    return (unsigned)__cvta_generic_to_shared(p);
}
__device__ __forceinline__ void mma_tf32(float* c, unsigned a0, unsigned a1,
                                         unsigned a2, unsigned a3,
                                         unsigned b0, unsigned b1) {
    asm volatile(
        "mma.sync.aligned.m16n8k8.row.col.f32.tf32.tf32.f32 "
        "{%0,%1,%2,%3}, {%4,%5,%6,%7}, {%8,%9}, {%0,%1,%2,%3};"
        : "+f"(c[0]), "+f"(c[1]), "+f"(c[2]), "+f"(c[3])
        : "r"(a0), "r"(a1), "r"(a2), "r"(a3), "r"(b0), "r"(b1));
}
__device__ __forceinline__ void mma_bf16(float* c, const unsigned* a, unsigned b0, unsigned b1) {
    asm volatile(
        "mma.sync.aligned.m16n8k16.row.col.f32.bf16.bf16.f32 "
        "{%0,%1,%2,%3}, {%4,%5,%6,%7}, {%8,%9}, {%0,%1,%2,%3};"
        : "+f"(c[0]), "+f"(c[1]), "+f"(c[2]), "+f"(c[3])
        : "r"(a[0]), "r"(a[1]), "r"(a[2]), "r"(a[3]), "r"(b0), "r"(b1));
}
__device__ __forceinline__ void ldsm4(unsigned* r, unsigned addr) {
    asm volatile("ldmatrix.sync.aligned.m8n8.x4.shared.b16 {%0,%1,%2,%3}, [%4];"
                 : "=r"(r[0]), "=r"(r[1]), "=r"(r[2]), "=r"(r[3]) : "r"(addr));
}

// ======================= generic NN tf32 GEMM (unchanged) ===================
template <bool SCALE>
__global__ __launch_bounds__(256, 2) void gemm_nn(
    const float* __restrict__ A, const float* __restrict__ B, float* __restrict__ C,
    int K, int lda, int ldb, int ldc, float alpha, const float* __restrict__ cs)
{
    __shared__ unsigned As[128 * 24];
    __shared__ unsigned Bs[16 * 136];

    const int tid = threadIdx.x, lane = tid & 31, wid = tid >> 5;
    const int wm = wid & 1, wn = wid >> 1, qr = lane >> 2, qc = lane & 3;
    const int bm0 = blockIdx.y * 128, bn0 = blockIdx.x * 128;
    const int arow = tid >> 1, akg = (tid & 1);
    const int nb = (tid & 31) * 4, kb = tid >> 5;

    float4 rA[2], rB[2];

    auto loadAB = [&](int t) {
        const float* ap = A + (long)(bm0 + arow) * lda + t + akg * 8;
        float4 v0 = *(const float4*)(ap);
        float4 v1 = *(const float4*)(ap + 4);
        if (SCALE) {
            int mg = bm0 + arow;
            int b = mg >> 11, s = mg & (SEQ - 1);
            int h = (t + akg * 8) >> 6;
            float sc = cs[(((long)b << 4) + h) * SEQ + s];
            v0.x *= sc; v0.y *= sc; v0.z *= sc; v0.w *= sc;
            v1.x *= sc; v1.y *= sc; v1.z *= sc; v1.w *= sc;
        }
        rA[0] = v0; rA[1] = v1;
#pragma unroll
        for (int rr = 0; rr < 2; rr++) {
            int k = kb + rr * 8;
            rB[rr] = *(const float4*)(B + (long)(t + k) * ldb + bn0 + nb);
        }
    };
    loadAB(0);

    float acc[4][4][4];
#pragma unroll
    for (int i = 0; i < 4; i++)
#pragma unroll
        for (int j = 0; j < 4; j++)
#pragma unroll
            for (int f = 0; f < 4; f++) acc[i][j][f] = 0.f;

#pragma unroll 1
    for (int t = 0; t < K; t += 16) {
        {
            int base = arow * 24 + akg * 8;
            *(uint4*)&As[base] =
                make_uint4(f2t(rA[0].x), f2t(rA[1].x), f2t(rA[0].y), f2t(rA[1].y));
            *(uint4*)&As[base + 4] =
                make_uint4(f2t(rA[0].z), f2t(rA[1].z), f2t(rA[0].w), f2t(rA[1].w));
#pragma unroll
            for (int rr = 0; rr < 2; rr++) {
                int k = kb + rr * 8;
                *(uint4*)&Bs[k * 136 + nb] =
                    make_uint4(f2t(rB[rr].x), f2t(rB[rr].y), f2t(rB[rr].z), f2t(rB[rr].w));
            }
        }
        __syncthreads();
        if (t + 16 < K) loadAB(t + 16);

#pragma unroll
        for (int g = 0; g < 2; g++) {
            int ks = g * 8;
            uint2 pa0[4], pa1[4];
            unsigned bf[4][2];
#pragma unroll
            for (int i = 0; i < 4; i++) {
                int mr = wm * 64 + i * 16 + qr;
                pa0[i] = *(const uint2*)&As[mr * 24 + g * 8 + qc * 2];
                pa1[i] = *(const uint2*)&As[(mr + 8) * 24 + g * 8 + qc * 2];
            }
#pragma unroll
            for (int j = 0; j < 4; j++) {
                int nc = wn * 32 + j * 8 + qr;
                bf[j][0] = Bs[(ks + qc) * 136 + nc];
                bf[j][1] = Bs[(ks + 4 + qc) * 136 + nc];
            }
#pragma unroll
            for (int i = 0; i < 4; i++)
#pragma unroll
                for (int j = 0; j < 4; j++)
                    mma_tf32(acc[i][j], pa0[i].x, pa1[i].x, pa0[i].y, pa1[i].y,
                             bf[j][0], bf[j][1]);
        }
        __syncthreads();
    }

#pragma unroll
    for (int i = 0; i < 4; i++) {
        long row = bm0 + wm * 64 + i * 16 + qr;
#pragma unroll
        for (int j = 0; j < 4; j++) {
            int col = bn0 + wn * 32 + j * 8 + 2 * qc;
            *(float2*)(C + row * ldc + col) =
                make_float2(alpha * acc[i][j][0], alpha * acc[i][j][1]);
            *(float2*)(C + (row + 8) * ldc + col) =
                make_float2(alpha * acc[i][j][2], alpha * acc[i][j][3]);
        }
    }
}

// ======================= fp32 qkv -> bf16 Q,K copies ========================
__global__ __launch_bounds__(256) void cvt_kernel(
    const float* __restrict__ qkv, uint4* __restrict__ q16, uint4* __restrict__ k16)
{
    long i = (long)blockIdx.x * 256 + threadIdx.x;   // over BS*1024/8
    long bs = i >> 7;
    int c8 = (int)(i & 127) * 8;
    const float* qp = qkv + bs * F3 + c8;
    const float* kp = qp + HID;
    float4 q0 = *(const float4*)qp, q1 = *(const float4*)(qp + 4);
    float4 k0 = *(const float4*)kp, k1 = *(const float4*)(kp + 4);
    __nv_bfloat162 a = __floats2bfloat162_rn(q0.x, q0.y);
    __nv_bfloat162 b = __floats2bfloat162_rn(q0.z, q0.w);
    __nv_bfloat162 c = __floats2bfloat162_rn(q1.x, q1.y);
    __nv_bfloat162 d = __floats2bfloat162_rn(q1.z, q1.w);
    q16[i] = make_uint4(*(unsigned*)&a, *(unsigned*)&b, *(unsigned*)&c, *(unsigned*)&d);
    a = __floats2bfloat162_rn(k0.x, k0.y);
    b = __floats2bfloat162_rn(k0.z, k0.w);
    c = __floats2bfloat162_rn(k1.x, k1.y);
    d = __floats2bfloat162_rn(k1.z, k1.w);
    k16[i] = make_uint4(*(unsigned*)&a, *(unsigned*)&b, *(unsigned*)&c, *(unsigned*)&d);
}

// ======================= bf16 QK^T pass (ldmatrix + m16n8k16) ===============
// MODE 1: Z[q] += sum_k exp(s_qk);  MODE 2: colsum[k] += sum_q exp(s_qk)/Z[q]
// smem tiles: [128 rows][64 halves], 16B-granule xor swizzle: g' = g ^ (row&7)
template <int MODE>
__global__ __launch_bounds__(256, 2) void qk_kernel(
    const uint4* __restrict__ Q16, const uint4* __restrict__ K16,
    float* __restrict__ Z, float* __restrict__ colsum)
{
    __shared__ uint4 Qs[128 * 8];      // 16 KB
    __shared__ uint4 Ks[128 * 8];      // 16 KB
    __shared__ float s_red[512];

    const int tid = threadIdx.x, lane = tid & 31, wid = tid >> 5;
    const int wm = wid & 1, wn = wid >> 1, qr = lane >> 2, qc = lane & 3;
    const int bz = blockIdx.z;
    const int b = bz >> 4, h = bz & 15;
    const int bm0 = blockIdx.y * 128, bn0 = blockIdx.x * 128;

    // row base in uint4 units: one (b,s) row of Q16 = 128 uint4; head offset h*8
    const uint4* Qg = Q16 + (long)b * SEQ * 128 + h * 8;
    const uint4* Kg = K16 + (long)b * SEQ * 128 + h * 8;

    const int cg = tid & 7, rb = tid >> 3;     // granule, row-group
#pragma unroll
    for (int r = 0; r < 4; r++) {
        int row = rb + r * 32;
        uint4 vq = Qg[(long)(bm0 + row) * 128 + cg];
        uint4 vk = Kg[(long)(bn0 + row) * 128 + cg];
        int sw = row * 8 + (cg ^ (row & 7));
        Qs[sw] = vq;
        Ks[sw] = vk;
    }
    if (MODE == 2 && tid < 128)
        s_red[tid] = 1.0f / Z[(long)bz * SEQ + bm0 + tid];
    __syncthreads();

    float izreg[4][2];
    if (MODE == 2) {
#pragma unroll
        for (int i = 0; i < 4; i++)
#pragma unroll
            for (int h2 = 0; h2 < 2; h2++)
                izreg[i][h2] = s_red[wm * 64 + i * 16 + h2 * 8 + qr];
    }

    float acc[4][4][4];
#pragma unroll
    for (int i = 0; i < 4; i++)
#pragma unroll
        for (int j = 0; j < 4; j++)
#pragma unroll
            for (int f = 0; f < 4; f++) acc[i][j][f] = 0.f;

    // per-lane ldmatrix row/granule-base components
    const int grp = lane >> 3, lrow = lane & 7;
    const int a_roff = (grp & 1) * 8, a_kg = grp >> 1;   // A: groups (m-half, k-half)
    const int b_roff = (grp >> 1) * 8, b_kg = grp & 1;   // B: groups (n-half, k-half)

#pragma unroll
    for (int g = 0; g < 4; g++) {            // k-step = 16 halves = 2 granules
        unsigned af[4][4], bfr[2][4];
#pragma unroll
        for (int i = 0; i < 4; i++) {
            int row = wm * 64 + i * 16 + lrow + a_roff;
            int gr = (2 * g + a_kg) ^ (row & 7);
            ldsm4(af[i], sptr(&Qs[row * 8 + gr]));
        }
#pragma unroll
        for (int jp = 0; jp < 2; jp++) {
            int row = wn * 32 + jp * 16 + lrow + b_roff;
            int gr = (2 * g + b_kg) ^ (row & 7);
            ldsm4(bfr[jp], sptr(&Ks[row * 8 + gr]));
        }
#pragma unroll
        for (int i = 0; i < 4; i++)
#pragma unroll
            for (int jp = 0; jp < 2; jp++) {
                mma_bf16(acc[i][jp * 2 + 0], af[i], bfr[jp][0], bfr[jp][1]);
                mma_bf16(acc[i][jp * 2 + 1], af[i], bfr[jp][2], bfr[jp][3]);
            }
    }

    if (MODE == 1) {
        float lz[4][2];
#pragma unroll
        for (int i = 0; i < 4; i++)
#pragma unroll
            for (int h2 = 0; h2 < 2; h2++) {
                float z = 0.f;
#pragma unroll
                for (int j = 0; j < 4; j++) {
                    z += ex2f(acc[i][j][2 * h2]     * C2EXP);
                    z += ex2f(acc[i][j][2 * h2 + 1] * C2EXP);
                }
                lz[i][h2] = z;
            }
#pragma unroll
        for (int d = 1; d <= 2; d <<= 1)
#pragma unroll
            for (int i = 0; i < 4; i++)
#pragma unroll
                for (int h2 = 0; h2 < 2; h2++)
                    lz[i][h2] += __shfl_xor_sync(0xffffffffu, lz[i][h2], d);
        __syncthreads();
        if (qc == 0)
#pragma unroll
            for (int i = 0; i < 4; i++)
#pragma unroll
                for (int h2 = 0; h2 < 2; h2++)
                    s_red[wn * 128 + wm * 64 + i * 16 + h2 * 8 + qr] = lz[i][h2];
        __syncthreads();
        if (tid < 128) {
            float z = s_red[tid] + s_red[128 + tid] + s_red[256 + tid] + s_red[384 + tid];
            atomicAdd(&Z[(long)bz * SEQ + bm0 + tid], z);
        }
    }

    if (MODE == 2) {
        float cs[4][2];
#pragma unroll
        for (int j = 0; j < 4; j++) { cs[j][0] = 0.f; cs[j][1] = 0.f; }
#pragma unroll
        for (int i = 0; i < 4; i++)
#pragma unroll
            for (int h2 = 0; h2 < 2; h2++) {
                float iz = izreg[i][h2];
#pragma unroll
                for (int j = 0; j < 4; j++) {
                    cs[j][0] += ex2f(acc[i][j][2 * h2]     * C2EXP) * iz;
                    cs[j][1] += ex2f(acc[i][j][2 * h2 + 1] * C2EXP) * iz;
                }
            }
#pragma unroll
        for (int d = 4; d <= 16; d <<= 1)
#pragma unroll
            for (int j = 0; j < 4; j++) {
                cs[j][0] += __shfl_xor_sync(0xffffffffu, cs[j][0], d);
                cs[j][1] += __shfl_xor_sync(0xffffffffu, cs[j][1], d);
            }
        if (qr == 0) {
#pragma unroll
            for (int j = 0; j < 4; j++) {
                int col = bn0 + wn * 32 + j * 8 + 2 * qc;
                atomicAdd(&colsum[(long)bz * SEQ + col],     cs[j][0]);
                atomicAdd(&colsum[(long)bz * SEQ + col + 1], cs[j][1]);
            }
        }
    }
}

// ---------------- zero accumulators ----------------------------------------
__global__ void zero_kernel(float* __restrict__ z, float* __restrict__ cs)
{
    int i = blockIdx.x * 256 + threadIdx.x;
    if (i < NBH * SEQ) { z[i] = 0.f; cs[i] = 0.f; }
}

// ---------------- launcher --------------------------------------------------
extern "C" void kernel_launch(void* const* d_in, const int* in_sizes, int n_in,
                              void* d_out, int out_size)
{
    const float* x     = (const float*)d_in[0];
    const float* w_qkv = (const float*)d_in[1];
    const float* w_o   = (const float*)d_in[2];
    float* out = (float*)d_out;

    float *p_qkv, *p_z, *p_cs;
    uint4 *p_q16, *p_k16;
    cudaGetSymbolAddress((void**)&p_qkv, g_qkv);
    cudaGetSymbolAddress((void**)&p_z,   g_z);
    cudaGetSymbolAddress((void**)&p_cs,  g_colsum);
    cudaGetSymbolAddress((void**)&p_q16, g_q16);
    cudaGetSymbolAddress((void**)&p_k16, g_k16);

    dim3 blk(256);

    // 0. zero Z + colsum accumulators
    zero_kernel<<<(NBH * SEQ + 255) / 256, blk>>>(p_z, p_cs);

    // 1. qkv = x @ w_qkv  (tf32)
    gemm_nn<false><<<dim3(F3 / 128, BS / 128), blk>>>(
        x, w_qkv, p_qkv, HID, HID, F3, F3, 1.0f, nullptr);

    // 1b. bf16 copies of Q, K
    cvt_kernel<<<(int)(((long)BS * HID / 8) / 256), blk>>>(p_qkv, p_q16, p_k16);

    // 2. pass 1: Z[q] = sum_k exp(q.k/8)   (bf16 tensor cores)
    qk_kernel<1><<<dim3(SEQ / 128, SEQ / 128, NBH), blk>>>(p_q16, p_k16, p_z, nullptr);

    // 3. pass 2: colsum[k] = sum_q exp(q.k/8)/Z[q]
    qk_kernel<2><<<dim3(SEQ / 128, SEQ / 128, NBH), blk>>>(p_q16, p_k16, p_z, p_cs);

    // 4. out = (v * colsum) @ w_o  (tf32, scale fused into A-load)
    gemm_nn<true><<<dim3(HID / 128, BS / 128), blk>>>(
        p_qkv + 2 * HID, w_o, out, HID, F3, HID, HID, 1.0f, p_cs);
}